// round 9
// baseline (speedup 1.0000x reference)
#include <cuda_runtime.h>
#include <math.h>
#include <stdint.h>

#define N_LEVELS 16
#define TABLE_SIZE (1u << 19)
#define HASH_MASK 0x7FFFFu
#define NPTS 1048576
#define PRIME_Y 2654435761u
#define PRIME_Z 805459861u

#define BINS_PER_AXIS 64
#define NBINS (BINS_PER_AXIS * BINS_PER_AXIS * BINS_PER_AXIS)

struct ResArr { float r[N_LEVELS]; };

// Scratch (static device globals: allowed; no allocation APIs)
__device__ unsigned d_count[NBINS];   // counts, then exclusive offsets (in place)
__device__ unsigned d_slot[NPTS];     // (bin << 14) | rank-within-bin
__device__ float4   d_xs[NPTS];       // reordered points: (x, y, z, bits(point_id))
__device__ unsigned d_cursor;

__device__ __forceinline__ unsigned spread3(unsigned v) {
    v = (v | (v << 16)) & 0x030000FFu;
    v = (v | (v << 8))  & 0x0300F00Fu;
    v = (v | (v << 4))  & 0x030C30C3u;
    v = (v | (v << 2))  & 0x09249249u;
    return v;
}

__device__ __forceinline__ unsigned bin_of(float px, float py, float pz,
                                           float b0x, float b0y, float b0z,
                                           float ivx, float ivy, float ivz) {
    float ux = (px - b0x) * ivx;
    float uy = (py - b0y) * ivy;
    float uz = (pz - b0z) * ivz;
    int bx = min(BINS_PER_AXIS - 1, max(0, (int)floorf(ux * BINS_PER_AXIS)));
    int by = min(BINS_PER_AXIS - 1, max(0, (int)floorf(uy * BINS_PER_AXIS)));
    int bz = min(BINS_PER_AXIS - 1, max(0, (int)floorf(uz * BINS_PER_AXIS)));
    return spread3((unsigned)bx) | (spread3((unsigned)by) << 1) | (spread3((unsigned)bz) << 2);
}

__global__ void k_zero() {
    int i = blockIdx.x * blockDim.x + threadIdx.x;
    if (i < NBINS / 4) ((uint4*)d_count)[i] = make_uint4(0u, 0u, 0u, 0u);
    if (i == 0) d_cursor = 0u;
}

__global__ void k_count(const float* __restrict__ x,
                        const float* __restrict__ bbox,
                        float* __restrict__ mask_out, int write_mask) {
    int i = blockIdx.x * blockDim.x + threadIdx.x;
    if (i >= NPTS) return;
    float b0x = __ldg(bbox + 0), b0y = __ldg(bbox + 1), b0z = __ldg(bbox + 2);
    float b1x = __ldg(bbox + 3), b1y = __ldg(bbox + 4), b1z = __ldg(bbox + 5);
    float px = __ldg(x + 3 * i + 0);
    float py = __ldg(x + 3 * i + 1);
    float pz = __ldg(x + 3 * i + 2);
    if (write_mask) {
        bool m = (px >= b0x) && (px <= b1x) && (py >= b0y) && (py <= b1y) &&
                 (pz >= b0z) && (pz <= b1z);
        mask_out[i] = m ? 1.0f : 0.0f;
    }
    float ivx = 1.0f / (b1x - b0x), ivy = 1.0f / (b1y - b0y), ivz = 1.0f / (b1z - b0z);
    unsigned b = bin_of(px, py, pz, b0x, b0y, b0z, ivx, ivy, ivz);
    unsigned rank = atomicAdd(&d_count[b], 1u);
    d_slot[i] = (b << 14) | (rank & 0x3FFFu);
}

__global__ void k_offsets() {
    int t = blockIdx.x * blockDim.x + threadIdx.x;
    if (t >= NBINS) return;
    int lane = threadIdx.x & 31;
    unsigned v = d_count[t];
    unsigned pre = v;
#pragma unroll
    for (int d = 1; d < 32; d <<= 1) {
        unsigned n = __shfl_up_sync(0xFFFFFFFFu, pre, d);
        if (lane >= d) pre += n;
    }
    unsigned total = __shfl_sync(0xFFFFFFFFu, pre, 31);
    unsigned base = 0;
    if (lane == 31) base = atomicAdd(&d_cursor, total);
    base = __shfl_sync(0xFFFFFFFFu, base, 31);
    d_count[t] = base + pre - v;   // exclusive offset
}

__global__ void k_scatter(const float* __restrict__ x) {
    int i = blockIdx.x * blockDim.x + threadIdx.x;
    if (i >= NPTS) return;
    unsigned s = d_slot[i];
    unsigned b = s >> 14;
    unsigned rank = s & 0x3FFFu;
    unsigned dst = d_count[b] + rank;
    float px = __ldcs(x + 3 * i + 0);
    float py = __ldcs(x + 3 * i + 1);
    float pz = __ldcs(x + 3 * i + 2);
    d_xs[dst] = make_float4(px, py, pz, __uint_as_float((unsigned)i));
}

// Shared level-octet worker: warp = 16 points x 2 x-sides; adjacent lanes hold
// the two x-corner indices of the same (y,z) corner -> sector/line merge in the
// L1 coalescer. shfl_xor completes the x-lerp; side s stores its 4 levels.
// Levels processed: [lbase, lbase+8). Output floats [fbase, fbase+16) of the row.
template <int LBASE>
__device__ __forceinline__ void embed8(
    float px, float py, float pz, int p, int side,
    const float2* __restrict__ emb, const float* __restrict__ bbox,
    float* __restrict__ out, const ResArr& res)
{
    float b0x = __ldg(bbox + 0), b0y = __ldg(bbox + 1), b0z = __ldg(bbox + 2);
    float b1x = __ldg(bbox + 3), b1y = __ldg(bbox + 4), b1z = __ldg(bbox + 5);

    float cx = fminf(fmaxf(px, b0x), b1x);
    float cy = fminf(fmaxf(py, b0y), b1y);
    float cz = fminf(fmaxf(pz, b0z), b1z);

    float invx = 1.0f / (b1x - b0x);
    float invy = 1.0f / (b1y - b0y);
    float invz = 1.0f / (b1z - b0z);

    float ux = (cx - b0x) * invx;
    float uy = (cy - b0y) * invy;
    float uz = (cz - b0z) * invz;
    float gx = (px - b0x) * invx;   // w numerator uses UNCLIPPED x (matches ref)
    float gy = (py - b0y) * invy;
    float gz = (pz - b0z) * invz;

    float accx[8], accy[8];

#pragma unroll
    for (int j = 0; j < 8; ++j) {
        int level = LBASE + j;
        float r = res.r[level];

        float fx = floorf(ux * r), fy = floorf(uy * r), fz = floorf(uz * r);
        float wx = fmaf(gx, r, -fx);
        float wy = fmaf(gy, r, -fy);
        float wz = fmaf(gz, r, -fz);

        unsigned ix = (unsigned)(int)fx + (unsigned)side;
        unsigned iy = (unsigned)(int)fy;
        unsigned iz = (unsigned)(int)fz;
        unsigned hy0 = iy * PRIME_Y, hy1 = hy0 + PRIME_Y;
        unsigned hz0 = iz * PRIME_Z, hz1 = hz0 + PRIME_Z;

        const float2* t2 = emb + (size_t)level * TABLE_SIZE;

        float2 v0 = __ldg(t2 + ((ix ^ hy0 ^ hz0) & HASH_MASK));
        float2 v1 = __ldg(t2 + ((ix ^ hy0 ^ hz1) & HASH_MASK));
        float2 v2 = __ldg(t2 + ((ix ^ hy1 ^ hz0) & HASH_MASK));
        float2 v3 = __ldg(t2 + ((ix ^ hy1 ^ hz1) & HASH_MASK));

        float oy = 1.0f - wy, oz = 1.0f - wz;
        float xw = side ? wx : (1.0f - wx);

        float c0a = v0.x * oy + v2.x * wy, c0b = v0.y * oy + v2.y * wy;
        float c1a = v1.x * oy + v3.x * wy, c1b = v1.y * oy + v3.y * wy;
        float sa = (c0a * oz + c1a * wz) * xw;
        float sb = (c0b * oz + c1b * wz) * xw;

        sa += __shfl_xor_sync(0xFFFFFFFFu, sa, 1);
        sb += __shfl_xor_sync(0xFFFFFFFFu, sb, 1);

        accx[j] = sa;
        accy[j] = sb;
    }

    // side s stores levels j in [4s, 4s+4): floats [LBASE*2 + s*8, +8)
    int jb = side * 4;
    float4* o = (float4*)(out + (size_t)p * 32 + LBASE * 2 + side * 8);
    o[0] = make_float4(accx[jb + 0], accy[jb + 0], accx[jb + 1], accy[jb + 1]);
    o[1] = make_float4(accx[jb + 2], accy[jb + 2], accx[jb + 3], accy[jb + 3]);
}

// Fine levels 8..15: spatial sorting gives no dedup here (res >= 128), so run
// directly on UNSORTED points -> no dependency on the binning pipeline.
__global__ void __launch_bounds__(256) k_fine(
    const float* __restrict__ x,
    const float2* __restrict__ emb,
    const float* __restrict__ bbox,
    float* __restrict__ out,
    ResArr res)
{
    int t = threadIdx.x;
    int w = t >> 5, lane = t & 31;
    int q = lane >> 1, side = lane & 1;
    int p = blockIdx.x * 128 + w * 16 + q;   // consecutive ids: coalesced x, stores
    float px = __ldg(x + 3 * p + 0);
    float py = __ldg(x + 3 * p + 1);
    float pz = __ldg(x + 3 * p + 2);
    embed8<8>(px, py, pz, p, side, emb, bbox, out, res);
}

// Coarse levels 0..7 on sorted points (sort gives the warp-level address merge).
__global__ void __launch_bounds__(256) k_coarse(
    const float2* __restrict__ emb,
    const float* __restrict__ bbox,
    float* __restrict__ out,
    ResArr res)
{
    int t = threadIdx.x;
    int w = t >> 5, lane = t & 31;
    int q = lane >> 1, side = lane & 1;
    int point = blockIdx.x * 128 + w * 16 + q;
    float4 P = __ldg(&d_xs[point]);
    int p = (int)__float_as_uint(P.w);
    embed8<0>(P.x, P.y, P.z, p, side, emb, bbox, out, res);
}

extern "C" void kernel_launch(void* const* d_in, const int* in_sizes, int n_in,
                              void* d_out, int out_size) {
    const float*  x    = (const float*)d_in[0];
    const float2* emb  = (const float2*)d_in[1];
    const float*  bbox = (const float*)d_in[2];
    float* out = (float*)d_out;

    ResArr res;
    double b = exp((log(512.0) - log(16.0)) / 15.0);
    for (int l = 0; l < N_LEVELS; ++l) {
        res.r[l] = (float)floor(16.0 * pow(b, (double)l));
    }

    int write_mask = (out_size >= (int)(NPTS * 32 + NPTS)) ? 1 : 0;
    float* mask_out = out + (size_t)NPTS * 32;

    // Fork a side stream inside the capture: the DRAM-bound binning pipeline +
    // coarse kernel overlap with the L1-bound fine kernel on the main stream.
    cudaStream_t side;
    cudaStreamCreateWithFlags(&side, cudaStreamNonBlocking);
    cudaEvent_t ev0, ev1;
    cudaEventCreateWithFlags(&ev0, cudaEventDisableTiming);
    cudaEventCreateWithFlags(&ev1, cudaEventDisableTiming);

    cudaEventRecord(ev0, 0);
    cudaStreamWaitEvent(side, ev0, 0);

    // side stream: binning + coarse levels (needs sorted points)
    k_zero<<<(NBINS / 4 + 255) / 256, 256, 0, side>>>();
    k_count<<<(NPTS + 255) / 256, 256, 0, side>>>(x, bbox, mask_out, write_mask);
    k_offsets<<<(NBINS + 255) / 256, 256, 0, side>>>();
    k_scatter<<<(NPTS + 255) / 256, 256, 0, side>>>(x);
    k_coarse<<<NPTS / 128, 256, 0, side>>>(emb, bbox, out, res);
    cudaEventRecord(ev1, side);

    // main stream: fine levels on unsorted points (independent of binning)
    k_fine<<<NPTS / 128, 256>>>(x, emb, bbox, out, res);

    cudaStreamWaitEvent(0, ev1, 0);

    cudaEventDestroy(ev0);
    cudaEventDestroy(ev1);
    cudaStreamDestroy(side);
}

// round 10
// speedup vs baseline: 1.4902x; 1.4902x over previous
#include <cuda_runtime.h>
#include <math.h>
#include <stdint.h>

#define N_LEVELS 16
#define TABLE_SIZE (1u << 19)
#define HASH_MASK 0x7FFFFu
#define NPTS 1048576
#define PRIME_Y 2654435761u
#define PRIME_Z 805459861u

#define BINS_PER_AXIS 64
#define NBINS (BINS_PER_AXIS * BINS_PER_AXIS * BINS_PER_AXIS)

struct ResArr { float r[N_LEVELS]; };

// Scratch (static device globals: allowed; no allocation APIs)
__device__ unsigned d_count[NBINS];   // counts, then exclusive offsets (in place)
__device__ unsigned d_slot[NPTS];     // (bin << 14) | rank-within-bin
__device__ float4   d_xs[NPTS];       // reordered points: (x, y, z, bits(point_id))
__device__ unsigned d_cursor;

__device__ __forceinline__ unsigned spread3(unsigned v) {
    v = (v | (v << 16)) & 0x030000FFu;
    v = (v | (v << 8))  & 0x0300F00Fu;
    v = (v | (v << 4))  & 0x030C30C3u;
    v = (v | (v << 2))  & 0x09249249u;
    return v;
}

__device__ __forceinline__ unsigned bin_of(float px, float py, float pz,
                                           float b0x, float b0y, float b0z,
                                           float ivx, float ivy, float ivz) {
    float ux = (px - b0x) * ivx;
    float uy = (py - b0y) * ivy;
    float uz = (pz - b0z) * ivz;
    int bx = min(BINS_PER_AXIS - 1, max(0, (int)floorf(ux * BINS_PER_AXIS)));
    int by = min(BINS_PER_AXIS - 1, max(0, (int)floorf(uy * BINS_PER_AXIS)));
    int bz = min(BINS_PER_AXIS - 1, max(0, (int)floorf(uz * BINS_PER_AXIS)));
    return spread3((unsigned)bx) | (spread3((unsigned)by) << 1) | (spread3((unsigned)bz) << 2);
}

__global__ void k_zero() {
    int i = blockIdx.x * blockDim.x + threadIdx.x;
    if (i < NBINS / 4) ((uint4*)d_count)[i] = make_uint4(0u, 0u, 0u, 0u);
    if (i == 0) d_cursor = 0u;
}

__global__ void k_count(const float* __restrict__ x,
                        const float* __restrict__ bbox,
                        float* __restrict__ mask_out, int write_mask) {
    int i = blockIdx.x * blockDim.x + threadIdx.x;
    if (i >= NPTS) return;
    float b0x = __ldg(bbox + 0), b0y = __ldg(bbox + 1), b0z = __ldg(bbox + 2);
    float b1x = __ldg(bbox + 3), b1y = __ldg(bbox + 4), b1z = __ldg(bbox + 5);
    float px = __ldg(x + 3 * i + 0);
    float py = __ldg(x + 3 * i + 1);
    float pz = __ldg(x + 3 * i + 2);
    if (write_mask) {
        bool m = (px >= b0x) && (px <= b1x) && (py >= b0y) && (py <= b1y) &&
                 (pz >= b0z) && (pz <= b1z);
        mask_out[i] = m ? 1.0f : 0.0f;
    }
    float ivx = 1.0f / (b1x - b0x), ivy = 1.0f / (b1y - b0y), ivz = 1.0f / (b1z - b0z);
    unsigned b = bin_of(px, py, pz, b0x, b0y, b0z, ivx, ivy, ivz);
    unsigned rank = atomicAdd(&d_count[b], 1u);
    d_slot[i] = (b << 14) | (rank & 0x3FFFu);
}

__global__ void k_offsets() {
    int t = blockIdx.x * blockDim.x + threadIdx.x;
    if (t >= NBINS) return;
    int lane = threadIdx.x & 31;
    unsigned v = d_count[t];
    unsigned pre = v;
#pragma unroll
    for (int d = 1; d < 32; d <<= 1) {
        unsigned n = __shfl_up_sync(0xFFFFFFFFu, pre, d);
        if (lane >= d) pre += n;
    }
    unsigned total = __shfl_sync(0xFFFFFFFFu, pre, 31);
    unsigned base = 0;
    if (lane == 31) base = atomicAdd(&d_cursor, total);
    base = __shfl_sync(0xFFFFFFFFu, base, 31);
    d_count[t] = base + pre - v;   // exclusive offset
}

__global__ void k_scatter(const float* __restrict__ x) {
    int i = blockIdx.x * blockDim.x + threadIdx.x;
    if (i >= NPTS) return;
    unsigned s = d_slot[i];
    unsigned b = s >> 14;
    unsigned rank = s & 0x3FFFu;
    unsigned dst = d_count[b] + rank;
    float px = __ldcs(x + 3 * i + 0);
    float py = __ldcs(x + 3 * i + 1);
    float pz = __ldcs(x + 3 * i + 2);
    d_xs[dst] = make_float4(px, py, pz, __uint_as_float((unsigned)i));
}

// Thread = (point, x-side) over ALL 16 levels. Warp = 16 sorted points x 2
// x-sides: adjacent lanes hold the two x-corner indices of the same (y,z)
// corner -> 32B-sector merge in the L1 coalescer (m=1,3 cases, p=3/4).
// shfl_xor completes the trilinear lerp; every 4 levels each side flushes one
// aligned float4, keeping register pressure low. Prologue runs 2x per point
// (vs 4x before).
__global__ void __launch_bounds__(256, 3) hash_embed_kernel(
    const float2* __restrict__ emb,
    const float* __restrict__ bbox,
    float* __restrict__ out,
    ResArr res)
{
    int t = threadIdx.x;
    int w = t >> 5, lane = t & 31;
    int q = lane >> 1, side = lane & 1;
    int point = blockIdx.x * 128 + w * 16 + q;

    float4 P = __ldg(&d_xs[point]);
    float px = P.x, py = P.y, pz = P.z;
    int p = (int)__float_as_uint(P.w);

    float b0x = __ldg(bbox + 0), b0y = __ldg(bbox + 1), b0z = __ldg(bbox + 2);
    float b1x = __ldg(bbox + 3), b1y = __ldg(bbox + 4), b1z = __ldg(bbox + 5);

    float cx = fminf(fmaxf(px, b0x), b1x);
    float cy = fminf(fmaxf(py, b0y), b1y);
    float cz = fminf(fmaxf(pz, b0z), b1z);

    float invx = 1.0f / (b1x - b0x);
    float invy = 1.0f / (b1y - b0y);
    float invz = 1.0f / (b1z - b0z);

    float ux = (cx - b0x) * invx;
    float uy = (cy - b0y) * invy;
    float uz = (cz - b0z) * invz;
    float gx = (px - b0x) * invx;   // w numerator uses UNCLIPPED x (matches ref)
    float gy = (py - b0y) * invy;
    float gz = (pz - b0z) * invz;

    float* orow = out + (size_t)p * 32 + side * 4;

#pragma unroll
    for (int jc = 0; jc < 4; ++jc) {       // 4 chunks of 4 levels
        float c[8];
#pragma unroll
        for (int j2 = 0; j2 < 4; ++j2) {
            int level = jc * 4 + j2;
            float r = res.r[level];

            float fx = floorf(ux * r), fy = floorf(uy * r), fz = floorf(uz * r);
            float wx = fmaf(gx, r, -fx);
            float wy = fmaf(gy, r, -fy);
            float wz = fmaf(gz, r, -fz);

            unsigned ix = (unsigned)(int)fx + (unsigned)side;
            unsigned iy = (unsigned)(int)fy;
            unsigned iz = (unsigned)(int)fz;
            unsigned hy0 = iy * PRIME_Y, hy1 = hy0 + PRIME_Y;
            unsigned hz0 = iz * PRIME_Z, hz1 = hz0 + PRIME_Z;

            const float2* t2 = emb + (size_t)level * TABLE_SIZE;

            // this side's 4 corners, (y,z) = 00,01,10,11 — identical order in
            // both lanes of a pair so the pairwise sector-merge happens
            float2 v0 = __ldg(t2 + ((ix ^ hy0 ^ hz0) & HASH_MASK));
            float2 v1 = __ldg(t2 + ((ix ^ hy0 ^ hz1) & HASH_MASK));
            float2 v2 = __ldg(t2 + ((ix ^ hy1 ^ hz0) & HASH_MASK));
            float2 v3 = __ldg(t2 + ((ix ^ hy1 ^ hz1) & HASH_MASK));

            float oy = 1.0f - wy, oz = 1.0f - wz;
            float xw = side ? wx : (1.0f - wx);

            float c0a = v0.x * oy + v2.x * wy, c0b = v0.y * oy + v2.y * wy;
            float c1a = v1.x * oy + v3.x * wy, c1b = v1.y * oy + v3.y * wy;
            float sa = (c0a * oz + c1a * wz) * xw;
            float sb = (c0b * oz + c1b * wz) * xw;

            sa += __shfl_xor_sync(0xFFFFFFFFu, sa, 1);
            sb += __shfl_xor_sync(0xFFFFFFFFu, sb, 1);

            c[j2 * 2 + 0] = sa;
            c[j2 * 2 + 1] = sb;
        }
        // both lanes hold all 8 chunk floats; side s stores its aligned half
        float4 v = side ? make_float4(c[4], c[5], c[6], c[7])
                        : make_float4(c[0], c[1], c[2], c[3]);
        *(float4*)(orow + jc * 8) = v;
    }
}

extern "C" void kernel_launch(void* const* d_in, const int* in_sizes, int n_in,
                              void* d_out, int out_size) {
    const float*  x    = (const float*)d_in[0];
    const float2* emb  = (const float2*)d_in[1];
    const float*  bbox = (const float*)d_in[2];
    float* out = (float*)d_out;

    // Resolutions: replicate numpy's double-precision exp/log/pow exactly.
    ResArr res;
    double b = exp((log(512.0) - log(16.0)) / 15.0);
    for (int l = 0; l < N_LEVELS; ++l) {
        res.r[l] = (float)floor(16.0 * pow(b, (double)l));
    }

    int write_mask = (out_size >= (int)(NPTS * 32 + NPTS)) ? 1 : 0;
    float* mask_out = out + (size_t)NPTS * 32;

    k_zero<<<(NBINS / 4 + 255) / 256, 256>>>();
    k_count<<<(NPTS + 255) / 256, 256>>>(x, bbox, mask_out, write_mask);
    k_offsets<<<(NBINS + 255) / 256, 256>>>();
    k_scatter<<<(NPTS + 255) / 256, 256>>>(x);

    // 128 points per block, 2 threads per point (2 x-sides, all 16 levels)
    hash_embed_kernel<<<NPTS / 128, 256>>>(emb, bbox, out, res);
}